// round 2
// baseline (speedup 1.0000x reference)
#include <cuda_runtime.h>
#include <math.h>

#define NB    128     // batch
#define NQ    16      // query tokens
#define ND    1024    // doc tokens
#define NE    300     // embedding dim
#define NK    11      // kernel bank size

#define TD    256     // doc tokens per block (main kernel)
#define KC    60      // k-chunk (floats) staged through smem; 5*60 = 300
#define NCH   5

// scratch (static __device__ arrays — no allocation allowed)
__device__ float g_qn[NB * NQ * NE];      // normalized query embeddings
__device__ float g_acc[NB * NK * NQ];     // per-(b,k,q) kernel sums

// ---------------------------------------------------------------------------
// Kernel 1: normalize query embeddings (warp per (b,q) row) + zero g_acc.
// grid: 256 blocks x 256 threads = 2048 warps = NB*NQ rows.
// ---------------------------------------------------------------------------
__global__ void __launch_bounds__(256) knrm_qnorm(
    const int* __restrict__ querytoks,
    const float* __restrict__ emb)
{
    const int tid = threadIdx.x;
    const int gt  = blockIdx.x * 256 + tid;

    if (gt < NB * NK * NQ) g_acc[gt] = 0.0f;

    const int row  = gt >> 5;          // 0..2047
    const int lane = tid & 31;
    if (row >= NB * NQ) return;

    const int tok = querytoks[row];
    const float4* src = (const float4*)(emb + (size_t)tok * NE); // 300 floats = 75 float4
    float4 v0 = src[lane];
    float4 v1 = src[32 + lane];
    float4 v2 = make_float4(0.f, 0.f, 0.f, 0.f);
    if (lane < 11) v2 = src[64 + lane];

    float ss = v0.x*v0.x + v0.y*v0.y + v0.z*v0.z + v0.w*v0.w;
    ss += v1.x*v1.x + v1.y*v1.y + v1.z*v1.z + v1.w*v1.w;
    ss += v2.x*v2.x + v2.y*v2.y + v2.z*v2.z + v2.w*v2.w;
    #pragma unroll
    for (int o = 16; o; o >>= 1) ss += __shfl_xor_sync(0xffffffffu, ss, o);

    const float rn = 1.0f / (sqrtf(ss) + 1e-9f);

    float4* dst = (float4*)(g_qn + (size_t)row * NE);
    v0.x *= rn; v0.y *= rn; v0.z *= rn; v0.w *= rn;
    v1.x *= rn; v1.y *= rn; v1.z *= rn; v1.w *= rn;
    dst[lane]      = v0;
    dst[32 + lane] = v1;
    if (lane < 11) {
        v2.x *= rn; v2.y *= rn; v2.z *= rn; v2.w *= rn;
        dst[64 + lane] = v2;
    }
}

// ---------------------------------------------------------------------------
// Kernel 2: fused gather + cosine-sim GEMM + RBF bank + reduction over d.
// grid: (ND/TD, NB) blocks x 256 threads.
// Thread (qg = tid/64, dg = tid%64) owns the 4x4 sim tile
//   q in {4*qg+j}, d in {d0 + dg + 64*i}.
// Doc chunk smem rows are KC=60 floats (240B stride -> conflict-free LDS.128).
// qg==0 warps also accumulate sum-of-squares for all 256 rows from the same
// LDS values (doc norm folded in after the K loop).
// ---------------------------------------------------------------------------
#define SMEM_FLOATS (TD*KC + NQ*NE + TD + 2*NK)   // 15360 + 4800 + 256 + 22 = 20438

__global__ void __launch_bounds__(256, 2) knrm_main(
    const int*   __restrict__ doctoks,
    const float* __restrict__ emb,
    const float* __restrict__ mus,
    const float* __restrict__ sigmas)
{
    extern __shared__ float sm[];
    float* dn    = sm;                 // [TD][KC]
    float* qn    = sm + TD * KC;       // [NQ][NE]
    float* rns   = qn + NQ * NE;       // [TD]
    float* mu_s  = rns + TD;           // [NK]
    float* isg_s = mu_s + NK;          // [NK]
    __shared__ int toks_s[TD];

    const int tid = threadIdx.x;
    const int b   = blockIdx.y;
    const int d0  = blockIdx.x * TD;

    // stage qn[b], doc token ids, and kernel params
    {
        const float4* qsrc = (const float4*)(g_qn + (size_t)b * NQ * NE);
        float4* qdst = (float4*)qn;
        #pragma unroll 2
        for (int i = tid; i < NQ * NE / 4; i += 256) qdst[i] = qsrc[i];
        if (tid < TD) toks_s[tid] = doctoks[b * ND + d0 + tid];
        if (tid < NK) {
            mu_s[tid] = mus[tid];
            float s = sigmas[tid];
            isg_s[tid] = -0.5f / (s * s);
        }
    }
    __syncthreads();

    const int qg = tid >> 6;   // 0..3 (warp-uniform)
    const int dg = tid & 63;

    float sims[16];
    #pragma unroll
    for (int i = 0; i < 16; ++i) sims[i] = 0.0f;
    float ss0 = 0.f, ss1 = 0.f, ss2 = 0.f, ss3 = 0.f;

    #pragma unroll 1
    for (int c = 0; c < NCH; ++c) {
        if (c) __syncthreads();
        // load doc chunk: 256 rows x 15 float4, row-major over threads
        #pragma unroll
        for (int j = 0; j < 15; ++j) {
            int idx = tid + 256 * j;
            int row = idx / 15;
            int col = idx - row * 15;
            const float4 v = *((const float4*)(emb + (size_t)toks_s[row] * NE + c * KC) + col);
            *((float4*)(dn + row * KC) + col) = v;
        }
        __syncthreads();

        const float* qb = qn + c * KC;
        #pragma unroll
        for (int kq = 0; kq < 15; ++kq) {
            const float4 dv0 = *((const float4*)(dn + (dg      ) * KC) + kq);
            const float4 dv1 = *((const float4*)(dn + (dg +  64) * KC) + kq);
            const float4 dv2 = *((const float4*)(dn + (dg + 128) * KC) + kq);
            const float4 dv3 = *((const float4*)(dn + (dg + 192) * KC) + kq);
            if (qg == 0) {   // warp-uniform branch: warps 0/1 compute row sumsq
                ss0 = fmaf(dv0.x,dv0.x,ss0); ss0 = fmaf(dv0.y,dv0.y,ss0);
                ss0 = fmaf(dv0.z,dv0.z,ss0); ss0 = fmaf(dv0.w,dv0.w,ss0);
                ss1 = fmaf(dv1.x,dv1.x,ss1); ss1 = fmaf(dv1.y,dv1.y,ss1);
                ss1 = fmaf(dv1.z,dv1.z,ss1); ss1 = fmaf(dv1.w,dv1.w,ss1);
                ss2 = fmaf(dv2.x,dv2.x,ss2); ss2 = fmaf(dv2.y,dv2.y,ss2);
                ss2 = fmaf(dv2.z,dv2.z,ss2); ss2 = fmaf(dv2.w,dv2.w,ss2);
                ss3 = fmaf(dv3.x,dv3.x,ss3); ss3 = fmaf(dv3.y,dv3.y,ss3);
                ss3 = fmaf(dv3.z,dv3.z,ss3); ss3 = fmaf(dv3.w,dv3.w,ss3);
            }
            #pragma unroll
            for (int j = 0; j < 4; ++j) {
                const float4 qv = *((const float4*)(qb + (qg * 4 + j) * NE) + kq);
                float a0 = sims[j*4+0], a1 = sims[j*4+1], a2 = sims[j*4+2], a3 = sims[j*4+3];
                a0 = fmaf(qv.x, dv0.x, a0); a1 = fmaf(qv.x, dv1.x, a1);
                a2 = fmaf(qv.x, dv2.x, a2); a3 = fmaf(qv.x, dv3.x, a3);
                a0 = fmaf(qv.y, dv0.y, a0); a1 = fmaf(qv.y, dv1.y, a1);
                a2 = fmaf(qv.y, dv2.y, a2); a3 = fmaf(qv.y, dv3.y, a3);
                a0 = fmaf(qv.z, dv0.z, a0); a1 = fmaf(qv.z, dv1.z, a1);
                a2 = fmaf(qv.z, dv2.z, a2); a3 = fmaf(qv.z, dv3.z, a3);
                a0 = fmaf(qv.w, dv0.w, a0); a1 = fmaf(qv.w, dv1.w, a1);
                a2 = fmaf(qv.w, dv2.w, a2); a3 = fmaf(qv.w, dv3.w, a3);
                sims[j*4+0] = a0; sims[j*4+1] = a1; sims[j*4+2] = a2; sims[j*4+3] = a3;
            }
        }
    }

    // doc norms (computed by qg==0 warps) -> smem -> everyone
    if (qg == 0) {
        rns[dg      ] = 1.0f / (sqrtf(ss0) + 1e-9f);
        rns[dg +  64] = 1.0f / (sqrtf(ss1) + 1e-9f);
        rns[dg + 128] = 1.0f / (sqrtf(ss2) + 1e-9f);
        rns[dg + 192] = 1.0f / (sqrtf(ss3) + 1e-9f);
    }
    __syncthreads();
    const float rn0 = rns[dg], rn1 = rns[dg + 64], rn2 = rns[dg + 128], rn3 = rns[dg + 192];
    #pragma unroll
    for (int j = 0; j < 4; ++j) {
        sims[j*4+0] *= rn0; sims[j*4+1] *= rn1; sims[j*4+2] *= rn2; sims[j*4+3] *= rn3;
    }

    // RBF bank + warp-level d-reduction + global atomic accumulation
    const int lane = tid & 31;
    float* accb = g_acc + b * NK * NQ;
    #pragma unroll
    for (int j = 0; j < 4; ++j) {
        #pragma unroll
        for (int k = 0; k < NK; ++k) {
            const float mu = mu_s[k];
            const float g  = isg_s[k];
            float e0 = sims[j*4+0] - mu, e1 = sims[j*4+1] - mu;
            float e2 = sims[j*4+2] - mu, e3 = sims[j*4+3] - mu;
            float v = __expf(g * e0 * e0) + __expf(g * e1 * e1)
                    + __expf(g * e2 * e2) + __expf(g * e3 * e3);
            #pragma unroll
            for (int o = 16; o; o >>= 1) v += __shfl_xor_sync(0xffffffffu, v, o);
            if (lane == 0) atomicAdd(accb + k * NQ + (qg * 4 + j), v);
        }
    }
}

// ---------------------------------------------------------------------------
// Kernel 3: mask + log + sum over q + FC.  One thread per batch element.
// ---------------------------------------------------------------------------
__global__ void __launch_bounds__(128) knrm_final(
    const int*   __restrict__ querytoks,
    const float* __restrict__ fc_w,
    const float* __restrict__ fc_b,
    float*       __restrict__ out)
{
    const int b = threadIdx.x;
    if (b >= NB) return;

    unsigned mask = 0;
    #pragma unroll
    for (int q = 0; q < NQ; ++q)
        mask |= (unsigned)(querytoks[b * NQ + q] != 0) << q;

    const float* accb = g_acc + b * NK * NQ;
    float score = fc_b[0];
    #pragma unroll
    for (int k = 0; k < NK; ++k) {
        float rk = 0.0f;
        #pragma unroll
        for (int q = 0; q < NQ; ++q) {
            if ((mask >> q) & 1u)
                rk += logf(accb[k * NQ + q] + 1e-6f);
        }
        score = fmaf(rk, fc_w[k], score);
    }
    out[b] = score;
}

// ---------------------------------------------------------------------------
extern "C" void kernel_launch(void* const* d_in, const int* in_sizes, int n_in,
                              void* d_out, int out_size)
{
    const int*   doctoks   = (const int*)  d_in[0];   // [128,1024] int32
    const int*   querytoks = (const int*)  d_in[1];   // [128,16]   int32
    // d_in[2] = query_idf (unused by the reference)
    const float* emb       = (const float*)d_in[3];   // [100000,300] f32
    const float* mus       = (const float*)d_in[4];   // [11] f32
    const float* sigmas    = (const float*)d_in[5];   // [11] f32
    const float* fc_w      = (const float*)d_in[6];   // [1,11] f32
    const float* fc_b      = (const float*)d_in[7];   // [1] f32
    float* out = (float*)d_out;                        // [128,1] f32

    const int smem_bytes = SMEM_FLOATS * (int)sizeof(float);
    cudaFuncSetAttribute(knrm_main, cudaFuncAttributeMaxDynamicSharedMemorySize, smem_bytes);

    knrm_qnorm<<<256, 256>>>(querytoks, emb);
    knrm_main<<<dim3(ND / TD, NB), 256, smem_bytes>>>(doctoks, emb, mus, sigmas);
    knrm_final<<<1, 128>>>(querytoks, fc_w, fc_b, out);
}

// round 6
// speedup vs baseline: 1.6701x; 1.6701x over previous
#include <cuda_runtime.h>
#include <math.h>

#define NB   128
#define NQ   16
#define ND   1024
#define NE   300
#define NK   11
#define TD   512     // doc tokens per half
#define KC   20      // k-chunk floats (5 float4)
#define NCH  15      // 300 / 20
#define KQ   5       // float4 per chunk row
#define NT   512     // threads per block

typedef unsigned long long u64;
union F2 { u64 u; float2 f; };

__device__ __forceinline__ u64 ffma2(u64 a, u64 b, u64 c) {
    u64 d;
    asm("fma.rn.f32x2 %0, %1, %2, %3;" : "=l"(d) : "l"(a), "l"(b), "l"(c));
    return d;
}
__device__ __forceinline__ float ex2f_(float x) {
    float y;
    asm("ex2.approx.ftz.f32 %0, %1;" : "=f"(y) : "f"(x));
    return y;
}

// smem layout (float units)
#define OFF_DN   0
#define OFF_QN   (OFF_DN + TD*KC)          // 10240
#define OFF_RNS  (OFF_QN + NQ*NE)          // +4800
#define OFF_ACC  (OFF_RNS + TD)            // +512
#define OFF_MU   (OFF_ACC + NK*NQ)         // +176
#define OFF_A    (OFF_MU + NK)
#define OFF_TOK  (OFF_A + NK)              // int region
#define OFF_QTOK (OFF_TOK + TD)
#define SMEM_FLOATS (OFF_QTOK + NQ)        // 16278 floats = 65112 B

__global__ void __launch_bounds__(NT) knrm_fused(
    const int*   __restrict__ doctoks,
    const int*   __restrict__ querytoks,
    const float* __restrict__ emb,
    const float* __restrict__ mus,
    const float* __restrict__ sigmas,
    const float* __restrict__ fc_w,
    const float* __restrict__ fc_b,
    float*       __restrict__ out)
{
    extern __shared__ float sm[];
    float* dn   = sm + OFF_DN;     // [TD][KC]
    float* qn   = sm + OFF_QN;     // [NQ][NE] normalized query embeddings
    float* rns  = sm + OFF_RNS;    // [TD] doc inverse norms
    float* acc  = sm + OFF_ACC;    // [NK][NQ] kernel sums
    float* mu_s = sm + OFF_MU;
    float* A_s  = sm + OFF_A;
    int*   toks = (int*)(sm + OFF_TOK);   // [TD]
    int*   qtok = (int*)(sm + OFF_QTOK);  // [NQ]

    const int tid  = threadIdx.x;
    const int b    = blockIdx.x;
    const int lane = tid & 31;
    const int wid  = tid >> 5;    // 0..15

    if (tid < NK) {
        mu_s[tid] = mus[tid];
        float s = sigmas[tid];
        A_s[tid] = -0.7213475204444817f / (s * s);   // -0.5*log2(e)/sigma^2
    }
    if (tid < NK * NQ) acc[tid] = 0.0f;

    // ---- query normalization: warp `wid` owns q row `wid` ----
    {
        const int tok = querytoks[b * NQ + wid];
        if (lane == 0) qtok[wid] = tok;
        const float4* src = (const float4*)(emb + (size_t)tok * NE);  // 75 float4
        float4 v0 = src[lane];
        float4 v1 = src[32 + lane];
        float4 v2 = make_float4(0.f, 0.f, 0.f, 0.f);
        if (lane < 11) v2 = src[64 + lane];

        float ss = v0.x*v0.x + v0.y*v0.y + v0.z*v0.z + v0.w*v0.w
                 + v1.x*v1.x + v1.y*v1.y + v1.z*v1.z + v1.w*v1.w
                 + v2.x*v2.x + v2.y*v2.y + v2.z*v2.z + v2.w*v2.w;
        #pragma unroll
        for (int o = 16; o; o >>= 1) ss += __shfl_xor_sync(0xffffffffu, ss, o);
        const float rn = 1.0f / (sqrtf(ss) + 1e-9f);

        float4* dst = (float4*)(qn + wid * NE);
        v0.x *= rn; v0.y *= rn; v0.z *= rn; v0.w *= rn;
        v1.x *= rn; v1.y *= rn; v1.z *= rn; v1.w *= rn;
        dst[lane]      = v0;
        dst[32 + lane] = v1;
        if (lane < 11) {
            v2.x *= rn; v2.y *= rn; v2.z *= rn; v2.w *= rn;
            dst[64 + lane] = v2;
        }
    }
    __syncthreads();

    const int qg = tid >> 8;     // 0..1  (8 q rows each)
    const int dg = tid & 255;    // d rows: dg, dg+256

    #pragma unroll 1
    for (int h = 0; h < 2; ++h) {
        toks[tid] = doctoks[b * ND + h * TD + tid];
        __syncthreads();

        u64 sims[16];
        #pragma unroll
        for (int i = 0; i < 16; ++i) sims[i] = 0ull;
        u64 ss0 = 0ull, ss1 = 0ull;

        // prefetch chunk 0 into registers
        float4 pf[KQ];
        #pragma unroll
        for (int j = 0; j < KQ; ++j) {
            const int idx = tid + NT * j;
            const int row = idx / KQ;
            const int col = idx - row * KQ;
            pf[j] = *((const float4*)(emb + (size_t)toks[row] * NE) + col);
        }

        #pragma unroll 1
        for (int c = 0; c < NCH; ++c) {
            // commit prefetched chunk to smem
            #pragma unroll
            for (int j = 0; j < KQ; ++j) {
                const int idx = tid + NT * j;
                const int row = idx / KQ;
                const int col = idx - row * KQ;
                *((float4*)(dn + row * KC) + col) = pf[j];
            }
            __syncthreads();

            // prefetch next chunk (overlaps with compute below)
            if (c + 1 < NCH) {
                #pragma unroll
                for (int j = 0; j < KQ; ++j) {
                    const int idx = tid + NT * j;
                    const int row = idx / KQ;
                    const int col = idx - row * KQ;
                    pf[j] = *((const float4*)(emb + (size_t)toks[row] * NE + (c + 1) * KC) + col);
                }
            }

            // compute: 8q x 2d register tile, packed f32x2 FMA
            #pragma unroll
            for (int kq = 0; kq < KQ; ++kq) {
                const ulonglong2 dv0 = *((const ulonglong2*)(dn + dg * KC) + kq);
                const ulonglong2 dv1 = *((const ulonglong2*)(dn + (dg + 256) * KC) + kq);
                if (qg == 0) {   // warp-uniform: warps 0..7 accumulate doc sumsq
                    ss0 = ffma2(dv0.x, dv0.x, ss0); ss0 = ffma2(dv0.y, dv0.y, ss0);
                    ss1 = ffma2(dv1.x, dv1.x, ss1); ss1 = ffma2(dv1.y, dv1.y, ss1);
                }
                #pragma unroll
                for (int j = 0; j < 8; ++j) {
                    const ulonglong2 qv =
                        *((const ulonglong2*)(qn + (qg * 8 + j) * NE + c * KC) + kq);
                    sims[j*2  ] = ffma2(qv.x, dv0.x, sims[j*2  ]);
                    sims[j*2  ] = ffma2(qv.y, dv0.y, sims[j*2  ]);
                    sims[j*2+1] = ffma2(qv.x, dv1.x, sims[j*2+1]);
                    sims[j*2+1] = ffma2(qv.y, dv1.y, sims[j*2+1]);
                }
            }
            __syncthreads();
        }

        // doc inverse norms
        if (qg == 0) {
            F2 t0; t0.u = ss0;
            F2 t1; t1.u = ss1;
            rns[dg      ] = 1.0f / (sqrtf(t0.f.x + t0.f.y) + 1e-9f);
            rns[dg + 256] = 1.0f / (sqrtf(t1.f.x + t1.f.y) + 1e-9f);
        }
        __syncthreads();
        const float rn0 = rns[dg], rn1 = rns[dg + 256];

        float simf[16];
        #pragma unroll
        for (int j = 0; j < 8; ++j) {
            F2 a; a.u = sims[j*2];
            F2 c2; c2.u = sims[j*2+1];
            simf[j*2  ] = (a.f.x  + a.f.y ) * rn0;
            simf[j*2+1] = (c2.f.x + c2.f.y) * rn1;
        }

        // RBF bank + warp d-reduction + smem accumulation
        #pragma unroll
        for (int k = 0; k < NK; ++k) {
            const float mu = mu_s[k];
            const float A  = A_s[k];
            #pragma unroll
            for (int j = 0; j < 8; ++j) {
                const float t0 = simf[j*2]   - mu;
                const float t1 = simf[j*2+1] - mu;
                float v = ex2f_(A * t0 * t0) + ex2f_(A * t1 * t1);
                #pragma unroll
                for (int o = 16; o; o >>= 1) v += __shfl_xor_sync(0xffffffffu, v, o);
                if (lane == 0) atomicAdd(&acc[k * NQ + qg * 8 + j], v);
            }
        }
        __syncthreads();
    }

    // ---- finalize: mask + log + sum_q + FC ----
    if (wid == 0) {
        float part = 0.0f;
        if (lane < NQ && qtok[lane] != 0) {
            #pragma unroll
            for (int k = 0; k < NK; ++k)
                part += fc_w[k] * __logf(acc[k * NQ + lane] + 1e-6f);
        }
        #pragma unroll
        for (int o = 16; o; o >>= 1) part += __shfl_xor_sync(0xffffffffu, part, o);
        if (lane == 0) out[b] = part + fc_b[0];
    }
}

extern "C" void kernel_launch(void* const* d_in, const int* in_sizes, int n_in,
                              void* d_out, int out_size)
{
    const int*   doctoks   = (const int*)  d_in[0];
    const int*   querytoks = (const int*)  d_in[1];
    // d_in[2] = query_idf (unused by the reference)
    const float* emb       = (const float*)d_in[3];
    const float* mus       = (const float*)d_in[4];
    const float* sigmas    = (const float*)d_in[5];
    const float* fc_w      = (const float*)d_in[6];
    const float* fc_b      = (const float*)d_in[7];
    float* out = (float*)d_out;

    const int smem_bytes = SMEM_FLOATS * (int)sizeof(float);
    cudaFuncSetAttribute(knrm_fused, cudaFuncAttributeMaxDynamicSharedMemorySize, smem_bytes);

    knrm_fused<<<NB, NT, smem_bytes>>>(doctoks, querytoks, emb, mus, sigmas,
                                       fc_w, fc_b, out);
}

// round 7
// speedup vs baseline: 1.6943x; 1.0145x over previous
#include <cuda_runtime.h>
#include <math.h>

#define NB   128
#define NQ   16
#define ND   1024
#define NE   300
#define NK   11
#define TD   512     // doc tokens per half
#define KC   20      // k-chunk floats (5 float4)
#define NCH  15      // 300 / 20
#define KQ   5       // float4 per chunk row
#define NT   512     // threads per block

typedef unsigned long long u64;
union F2 { u64 u; float2 f; };

__device__ __forceinline__ u64 ffma2(u64 a, u64 b, u64 c) {
    u64 d;
    asm("fma.rn.f32x2 %0, %1, %2, %3;" : "=l"(d) : "l"(a), "l"(b), "l"(c));
    return d;
}
__device__ __forceinline__ float ex2f_(float x) {
    float y;
    asm("ex2.approx.ftz.f32 %0, %1;" : "=f"(y) : "f"(x));
    return y;
}

// smem layout (float units)
#define OFF_DN   0
#define OFF_QN   (OFF_DN + TD*KC)          // 10240
#define OFF_RNS  (OFF_QN + NQ*NE)          // +4800
#define OFF_ACC  (OFF_RNS + TD)            // +512
#define OFF_MU   (OFF_ACC + NK*NQ)         // +176
#define OFF_A    (OFF_MU + NK)
#define OFF_TOK  (OFF_A + NK)              // int region
#define OFF_QTOK (OFF_TOK + TD)
#define SMEM_FLOATS (OFF_QTOK + NQ)        // 16278 floats = 65112 B

__global__ void __launch_bounds__(NT) knrm_fused(
    const int*   __restrict__ doctoks,
    const int*   __restrict__ querytoks,
    const float* __restrict__ emb,
    const float* __restrict__ mus,
    const float* __restrict__ sigmas,
    const float* __restrict__ fc_w,
    const float* __restrict__ fc_b,
    float*       __restrict__ out)
{
    extern __shared__ float sm[];
    float* dn   = sm + OFF_DN;     // [TD][KC]
    float* qn   = sm + OFF_QN;     // [NQ][NE] normalized query embeddings
    float* rns  = sm + OFF_RNS;    // [TD] doc inverse norms
    float* acc  = sm + OFF_ACC;    // [NK][NQ] kernel sums
    float* mu_s = sm + OFF_MU;
    float* A_s  = sm + OFF_A;
    int*   toks = (int*)(sm + OFF_TOK);   // [TD]
    int*   qtok = (int*)(sm + OFF_QTOK);  // [NQ]

    const int tid  = threadIdx.x;
    const int b    = blockIdx.x;
    const int lane = tid & 31;
    const int wid  = tid >> 5;    // 0..15

    if (tid < NK) {
        mu_s[tid] = mus[tid];
        float s = sigmas[tid];
        A_s[tid] = -0.7213475204444817f / (s * s);   // -0.5*log2(e)/sigma^2
    }
    if (tid < NK * NQ) acc[tid] = 0.0f;

    // ---- query normalization: warp `wid` owns q row `wid` ----
    {
        const int tok = querytoks[b * NQ + wid];
        if (lane == 0) qtok[wid] = tok;
        const float4* src = (const float4*)(emb + (size_t)tok * NE);  // 75 float4
        float4 v0 = src[lane];
        float4 v1 = src[32 + lane];
        float4 v2 = make_float4(0.f, 0.f, 0.f, 0.f);
        if (lane < 11) v2 = src[64 + lane];

        float ss = v0.x*v0.x + v0.y*v0.y + v0.z*v0.z + v0.w*v0.w
                 + v1.x*v1.x + v1.y*v1.y + v1.z*v1.z + v1.w*v1.w
                 + v2.x*v2.x + v2.y*v2.y + v2.z*v2.z + v2.w*v2.w;
        #pragma unroll
        for (int o = 16; o; o >>= 1) ss += __shfl_xor_sync(0xffffffffu, ss, o);
        const float rn = 1.0f / (sqrtf(ss) + 1e-9f);

        float4* dst = (float4*)(qn + wid * NE);
        v0.x *= rn; v0.y *= rn; v0.z *= rn; v0.w *= rn;
        v1.x *= rn; v1.y *= rn; v1.z *= rn; v1.w *= rn;
        dst[lane]      = v0;
        dst[32 + lane] = v1;
        if (lane < 11) {
            v2.x *= rn; v2.y *= rn; v2.z *= rn; v2.w *= rn;
            dst[64 + lane] = v2;
        }
    }
    __syncthreads();

    const int qg = tid >> 8;     // 0..1  (8 q rows each)
    const int dg = tid & 255;    // d rows: dg, dg+256

    #pragma unroll 1
    for (int h = 0; h < 2; ++h) {
        toks[tid] = doctoks[b * ND + h * TD + tid];
        __syncthreads();

        u64 sims[16];
        #pragma unroll
        for (int i = 0; i < 16; ++i) sims[i] = 0ull;
        u64 ss0 = 0ull, ss1 = 0ull;

        // prefetch chunk 0 into registers
        float4 pf[KQ];
        #pragma unroll
        for (int j = 0; j < KQ; ++j) {
            const int idx = tid + NT * j;
            const int row = idx / KQ;
            const int col = idx - row * KQ;
            pf[j] = *((const float4*)(emb + (size_t)toks[row] * NE) + col);
        }

        #pragma unroll 1
        for (int c = 0; c < NCH; ++c) {
            // commit prefetched chunk to smem
            #pragma unroll
            for (int j = 0; j < KQ; ++j) {
                const int idx = tid + NT * j;
                const int row = idx / KQ;
                const int col = idx - row * KQ;
                *((float4*)(dn + row * KC) + col) = pf[j];
            }
            __syncthreads();

            // prefetch next chunk (overlaps with compute below)
            if (c + 1 < NCH) {
                #pragma unroll
                for (int j = 0; j < KQ; ++j) {
                    const int idx = tid + NT * j;
                    const int row = idx / KQ;
                    const int col = idx - row * KQ;
                    pf[j] = *((const float4*)(emb + (size_t)toks[row] * NE + (c + 1) * KC) + col);
                }
            }

            // compute: 8q x 2d register tile, packed f32x2 FMA
            #pragma unroll
            for (int kq = 0; kq < KQ; ++kq) {
                const ulonglong2 dv0 = *((const ulonglong2*)(dn + dg * KC) + kq);
                const ulonglong2 dv1 = *((const ulonglong2*)(dn + (dg + 256) * KC) + kq);
                if (qg == 0) {   // warp-uniform: warps 0..7 accumulate doc sumsq
                    ss0 = ffma2(dv0.x, dv0.x, ss0); ss0 = ffma2(dv0.y, dv0.y, ss0);
                    ss1 = ffma2(dv1.x, dv1.x, ss1); ss1 = ffma2(dv1.y, dv1.y, ss1);
                }
                #pragma unroll
                for (int j = 0; j < 8; ++j) {
                    const ulonglong2 qv =
                        *((const ulonglong2*)(qn + (qg * 8 + j) * NE + c * KC) + kq);
                    sims[j*2  ] = ffma2(qv.x, dv0.x, sims[j*2  ]);
                    sims[j*2  ] = ffma2(qv.y, dv0.y, sims[j*2  ]);
                    sims[j*2+1] = ffma2(qv.x, dv1.x, sims[j*2+1]);
                    sims[j*2+1] = ffma2(qv.y, dv1.y, sims[j*2+1]);
                }
            }
            __syncthreads();
        }

        // doc inverse norms
        if (qg == 0) {
            F2 t0; t0.u = ss0;
            F2 t1; t1.u = ss1;
            rns[dg      ] = 1.0f / (sqrtf(t0.f.x + t0.f.y) + 1e-9f);
            rns[dg + 256] = 1.0f / (sqrtf(t1.f.x + t1.f.y) + 1e-9f);
        }
        __syncthreads();
        const float rn0 = rns[dg], rn1 = rns[dg + 256];

        float simf[16];
        #pragma unroll
        for (int j = 0; j < 8; ++j) {
            F2 a; a.u = sims[j*2];
            F2 c2; c2.u = sims[j*2+1];
            simf[j*2  ] = (a.f.x  + a.f.y ) * rn0;
            simf[j*2+1] = (c2.f.x + c2.f.y) * rn1;
        }

        // RBF bank + warp d-reduction + smem accumulation
        #pragma unroll
        for (int k = 0; k < NK; ++k) {
            const float mu = mu_s[k];
            const float A  = A_s[k];
            #pragma unroll
            for (int j = 0; j < 8; ++j) {
                const float t0 = simf[j*2]   - mu;
                const float t1 = simf[j*2+1] - mu;
                float v = ex2f_(A * t0 * t0) + ex2f_(A * t1 * t1);
                #pragma unroll
                for (int o = 16; o; o >>= 1) v += __shfl_xor_sync(0xffffffffu, v, o);
                if (lane == 0) atomicAdd(&acc[k * NQ + qg * 8 + j], v);
            }
        }
        __syncthreads();
    }

    // ---- finalize: mask + log + sum_q + FC ----
    if (wid == 0) {
        float part = 0.0f;
        if (lane < NQ && qtok[lane] != 0) {
            #pragma unroll
            for (int k = 0; k < NK; ++k)
                part += fc_w[k] * __logf(acc[k * NQ + lane] + 1e-6f);
        }
        #pragma unroll
        for (int o = 16; o; o >>= 1) part += __shfl_xor_sync(0xffffffffu, part, o);
        if (lane == 0) out[b] = part + fc_b[0];
    }
}

extern "C" void kernel_launch(void* const* d_in, const int* in_sizes, int n_in,
                              void* d_out, int out_size)
{
    const int*   doctoks   = (const int*)  d_in[0];
    const int*   querytoks = (const int*)  d_in[1];
    // d_in[2] = query_idf (unused by the reference)
    const float* emb       = (const float*)d_in[3];
    const float* mus       = (const float*)d_in[4];
    const float* sigmas    = (const float*)d_in[5];
    const float* fc_w      = (const float*)d_in[6];
    const float* fc_b      = (const float*)d_in[7];
    float* out = (float*)d_out;

    const int smem_bytes = SMEM_FLOATS * (int)sizeof(float);
    cudaFuncSetAttribute(knrm_fused, cudaFuncAttributeMaxDynamicSharedMemorySize, smem_bytes);

    knrm_fused<<<NB, NT, smem_bytes>>>(doctoks, querytoks, emb, mus, sigmas,
                                       fc_w, fc_b, out);
}